// round 8
// baseline (speedup 1.0000x reference)
#include <cuda_runtime.h>
#include <cstdint>

#define EMB_DIM   128
#define NB_WORDS  100000
#define MAX_BATCH 4096
#define NBINS     512          // bin = idx >> 8 -> 391 live bins, padded to 512
#define TILE_J    128
#define TILE_E    32

__device__ int d_sidx[MAX_BATCH];   // sorted position -> vocab index
__device__ int d_order[MAX_BATCH];  // sorted position -> batch row

// ---------------------------------------------------------------------------
// Kernel A: coarse counting sort by (idx >> 8). One block, 1024 threads.
// ---------------------------------------------------------------------------
__global__ void __launch_bounds__(1024)
order_kernel(const int* __restrict__ elt, int batch) {
    __shared__ int hist[NBINS];
    __shared__ int scan[NBINS];
    __shared__ int cursor[NBINS];
    const int tid = threadIdx.x;

    if (tid < NBINS) hist[tid] = 0;
    __syncthreads();

    for (int b = tid; b < batch; b += 1024)
        atomicAdd(&hist[elt[b] >> 8], 1);
    __syncthreads();

    if (tid < NBINS) scan[tid] = hist[tid];
    __syncthreads();

    // Hillis-Steele inclusive scan over 512 bins (9 steps)
    #pragma unroll
    for (int off = 1; off < NBINS; off <<= 1) {
        int add = 0;
        if (tid < NBINS && tid >= off) add = scan[tid - off];
        __syncthreads();
        if (tid < NBINS) scan[tid] += add;
        __syncthreads();
    }

    if (tid < NBINS) cursor[tid] = 0;
    __syncthreads();

    for (int b = tid; b < batch; b += 1024) {
        const int idx = elt[b];
        const int bin = idx >> 8;
        const int base = (bin == 0) ? 0 : scan[bin - 1];
        const int pos  = base + atomicAdd(&cursor[bin], 1);
        d_sidx[pos]  = idx;
        d_order[pos] = b;
    }
}

// ---------------------------------------------------------------------------
// Kernel B: tiled gather. Lanes = consecutive sorted positions j, so a warp's
// 32 simultaneous loads span ~3KB of one W row (DRAM row hits). smem transpose
// then fully-coalesced output stores.
// Grid: (batch/TILE_J, EMB_DIM/TILE_E) = (32, 4). Block: 128 threads.
// ---------------------------------------------------------------------------
__global__ void __launch_bounds__(128)
gather_kernel(const float* __restrict__ W,
              const float* __restrict__ bias,
              float* __restrict__ out,
              int batch) {
    __shared__ float tile[TILE_E][TILE_J + 1];   // +1 pad: conflict-free transpose
    __shared__ int   brow[TILE_J];

    const int tid = threadIdx.x;                 // 0..127
    const int j   = blockIdx.x * TILE_J + tid;   // sorted position for load phase
    const int e0  = blockIdx.y * TILE_E;

    // W loads: pin in L2 across graph replays, skip L1 (zero intra-launch reuse)
    uint64_t pol_last;
    asm volatile("createpolicy.fractional.L2::evict_last.b64 %0, 1.0;" : "=l"(pol_last));

    const bool valid = (j < batch);
    const int v = valid ? d_sidx[j] : 0;
    if (blockIdx.y == 0 || true) brow[tid] = valid ? d_order[j] : -1;

    // ---- load phase: 32 e-rows, lanes sweep sorted indices (quasi-sequential) ----
    const float* base = W + (size_t)e0 * NB_WORDS + v;
    #pragma unroll 8
    for (int ee = 0; ee < TILE_E; ee++) {
        float w;
        asm volatile("ld.global.nc.L2::cache_hint.f32 %0, [%1], %2;"
                     : "=f"(w) : "l"(base + (size_t)ee * NB_WORDS), "l"(pol_last));
        tile[ee][tid] = w;
    }
    __syncthreads();

    // ---- store phase: warp = 32 consecutive e's for one jj -> 128B coalesced ----
    const int lane = tid & 31;
    const int wrp  = tid >> 5;                   // 0..3
    const float bv = __ldg(&bias[e0 + lane]);

    #pragma unroll 8
    for (int jj = wrp; jj < TILE_J; jj += 4) {
        const int b = brow[jj];
        if (b >= 0)
            out[(size_t)b * EMB_DIM + e0 + lane] = tile[lane][jj] + bv;
    }
}

extern "C" void kernel_launch(void* const* d_in, const int* in_sizes, int n_in,
                              void* d_out, int out_size) {
    const int* elt  = (const int*)d_in[0];
    const float* W  = (const float*)d_in[1];
    const float* bv = (const float*)d_in[2];
    float* out      = (float*)d_out;

    int batch = in_sizes[0];
    if (batch > MAX_BATCH) batch = MAX_BATCH;    // scratch bound (spec: 4096)

    order_kernel<<<1, 1024>>>(elt, batch);

    dim3 grid((batch + TILE_J - 1) / TILE_J, EMB_DIM / TILE_E);
    gather_kernel<<<grid, 128>>>(W, bv, out, batch);
}

// round 9
// speedup vs baseline: 1.9140x; 1.9140x over previous
#include <cuda_runtime.h>
#include <cstdint>

#define EMB_DIM  128
#define NB_WORDS 100000

// out[b][e] = W[e * NB_WORDS + elt[b]] + bias[e]
// R7 launch shape (best measured): 4 batch rows per 512-thread block.
__global__ void __launch_bounds__(512)
time_embedding_kernel(const int* __restrict__ elt,
                      const float* __restrict__ W,
                      const float* __restrict__ bias,
                      float* __restrict__ out,
                      int batch) {
    const int e   = threadIdx.x & (EMB_DIM - 1);   // 0..127
    const int sub = threadIdx.x >> 7;              // 0..3
    const int b   = blockIdx.x * 4 + sub;
    if (b >= batch) return;

    // L2 policies: W lines evict_last (retained across graph replays),
    // output lines evict_first (streaming; don't displace W).
    uint64_t pol_last, pol_first;
    asm volatile("createpolicy.fractional.L2::evict_last.b64 %0, 1.0;"
                 : "=l"(pol_last));
    asm volatile("createpolicy.fractional.L2::evict_first.b64 %0, 1.0;"
                 : "=l"(pol_first));

    const int idx = __ldg(&elt[b]);                // warp-uniform broadcast
    const float* wp = &W[(size_t)e * NB_WORDS + idx];

    // Gather: zero L1 reuse (L1 flushed per launch anyway) -> skip L1
    // allocation entirely; pin the sector in L2 for replay reuse.
    float w;
    asm volatile("ld.global.nc.L1::no_allocate.L2::cache_hint.f32 %0, [%1], %2;"
                 : "=f"(w) : "l"(wp), "l"(pol_last));

    const float bv = __ldg(&bias[e]);
    float* op = &out[(size_t)b * EMB_DIM + e];
    const float val = w + bv;
    asm volatile("st.global.L2::cache_hint.f32 [%0], %1, %2;"
                 :: "l"(op), "f"(val), "l"(pol_first) : "memory");
}

extern "C" void kernel_launch(void* const* d_in, const int* in_sizes, int n_in,
                              void* d_out, int out_size) {
    const int* elt  = (const int*)d_in[0];
    const float* W  = (const float*)d_in[1];
    const float* bv = (const float*)d_in[2];
    float* out      = (float*)d_out;
    const int batch = in_sizes[0];                 // 4096

    time_embedding_kernel<<<(batch + 3) / 4, 512>>>(elt, W, bv, out, batch);
}

// round 10
// speedup vs baseline: 1.9632x; 1.0257x over previous
#include <cuda_runtime.h>
#include <cstdint>

#define EMB_DIM  128
#define NB_WORDS 100000

// out[b][e] = W[e * NB_WORDS + elt[b]] + bias[e]
// R7 launch shape (best measured): 4 batch rows per 512-thread block.
__global__ void __launch_bounds__(512)
time_embedding_kernel(const int* __restrict__ elt,
                      const float* __restrict__ W,
                      const float* __restrict__ bias,
                      float* __restrict__ out,
                      int batch) {
    const int e   = threadIdx.x & (EMB_DIM - 1);   // 0..127
    const int sub = threadIdx.x >> 7;              // 0..3
    const int b   = blockIdx.x * 4 + sub;
    if (b >= batch) return;

    // L2 policies: W lines evict_last (retained across graph replays),
    // output lines evict_first (streaming; don't displace W).
    uint64_t pol_last, pol_first;
    asm volatile("createpolicy.fractional.L2::evict_last.b64 %0, 1.0;"
                 : "=l"(pol_last));
    asm volatile("createpolicy.fractional.L2::evict_first.b64 %0, 1.0;"
                 : "=l"(pol_first));

    const int idx = __ldg(&elt[b]);                // warp-uniform broadcast
    const float* wp = &W[(size_t)e * NB_WORDS + idx];

    // Gather: request the minimum L2 fetch granularity (64B) instead of the
    // measured 128B/miss default -> cold DRAM traffic 37MB -> ~25MB.
    float w;
    asm volatile("ld.global.nc.L2::cache_hint.L2::64B.f32 %0, [%1], %2;"
                 : "=f"(w) : "l"(wp), "l"(pol_last));

    const float bv = __ldg(&bias[e]);
    float* op = &out[(size_t)b * EMB_DIM + e];
    const float val = w + bv;
    asm volatile("st.global.L2::cache_hint.f32 [%0], %1, %2;"
                 :: "l"(op), "f"(val), "l"(pol_first) : "memory");
}

extern "C" void kernel_launch(void* const* d_in, const int* in_sizes, int n_in,
                              void* d_out, int out_size) {
    const int* elt  = (const int*)d_in[0];
    const float* W  = (const float*)d_in[1];
    const float* bv = (const float*)d_in[2];
    float* out      = (float*)d_out;
    const int batch = in_sizes[0];                 // 4096

    time_embedding_kernel<<<(batch + 3) / 4, 512>>>(elt, W, bv, out, batch);
}